// round 13
// baseline (speedup 1.0000x reference)
#include <cuda_runtime.h>

#define NNODES 200000
#define NEDGES 3200000
#define HIDF 32
#define SCAN_BS 1024
#define NBLK_SCAN 196           // 196*1024 >= NNODES
#define CSR_CAP (NEDGES + 4 * NNODES)
typedef unsigned long long ull;

// ---------------- device scratch (static, zero-init at load) ----------------
__device__ int   g_degs[NNODES];   // src-degree
__device__ int   g_cnt[NNODES];    // dst-degree
__device__ int   g_cur[NNODES];    // scatter cursors
__device__ int   g_off[NNODES];    // padded CSR segment starts
__device__ int   g_total;          // atomic base for scan
__device__ float g_dinv[NNODES];
__device__ ull   g_csr[CSR_CAP];   // src[0:32) | fp32 w [32:64); pads re-zeroed per call
__device__ float g_A[NNODES * HIDF];
__device__ float g_B[NNODES * HIDF];
__device__ float g_D[NNODES * HIDF];

// ---------------- f32x2 helpers ----------------
__device__ __forceinline__ ull packf2(float x, float y) {
    ull r; asm("mov.b64 %0, {%1, %2};" : "=l"(r) : "f"(x), "f"(y)); return r;
}
__device__ __forceinline__ void unpackf2(ull v, float& x, float& y) {
    asm("mov.b64 {%0, %1}, %2;" : "=f"(x), "=f"(y) : "l"(v));
}
__device__ __forceinline__ void fmaf2(ull& a, ull b, ull c) {
    asm("fma.rn.f32x2 %0, %1, %2, %0;" : "+l"(a) : "l"(b), "l"(c));
}
__device__ __forceinline__ void fmaf2v(ull& a, ull w, float x, float y) {
    ull v; asm("mov.b64 %0, {%1, %2};" : "=l"(v) : "f"(x), "f"(y));
    asm("fma.rn.f32x2 %0, %1, %2, %0;" : "+l"(a) : "l"(w), "l"(v));
}

// probe: int32 data read as int64 -> lo + hi*2^32, out of [0,N) w.h.p.
__device__ __forceinline__ bool probe64(const void* ei) {
    const long long* p = (const long long*)ei;
    bool ok = true;
    for (int j = 0; j < 64; j++) { long long v = p[j]; ok &= (v >= 0 && v < NNODES); }
    return ok;
}

// L0: zero per-call state. Dedicated launch — MUST NOT be fused into any
// kernel whose other blocks read these arrays (learned in R12: cleanup in the
// final fused kernel raced with its own phase-1 g_cnt reads).
__global__ void k_zero() {
    int i = blockIdx.x * blockDim.x + threadIdx.x;
    if (i < NNODES / 4) {
        int4 z = make_int4(0, 0, 0, 0);
        reinterpret_cast<int4*>(g_degs)[i] = z;
        reinterpret_cast<int4*>(g_cnt)[i]  = z;
        reinterpret_cast<int4*>(g_cur)[i]  = z;
    }
    if (i == 0) g_total = 0;
}

// L1: degree histograms
__global__ void k_hist(const void* __restrict__ ei) {
    __shared__ int s64;
    if (threadIdx.x == 0) s64 = probe64(ei) ? 1 : 0;
    __syncthreads();
    int e = blockIdx.x * blockDim.x + threadIdx.x;
    if (e < NEDGES) {
        int s, d;
        if (s64) {
            s = (int)reinterpret_cast<const long long*>(ei)[e];
            d = (int)reinterpret_cast<const long long*>(ei)[NEDGES + e];
        } else {
            s = reinterpret_cast<const int*>(ei)[e];
            d = reinterpret_cast<const int*>(ei)[NEDGES + e];
        }
        s = min(max(s, 0), NNODES - 1);
        d = min(max(d, 0), NNODES - 1);
        atomicAdd(&g_degs[s], 1);
        atomicAdd(&g_cnt[d], 1);
    }
}

// L2: single-pass scan over PADDED counts + dinv + ZERO the pad slots.
__global__ __launch_bounds__(SCAN_BS) void k_scan() {
    __shared__ int s[SCAN_BS];
    __shared__ int sbase;
    int tid = threadIdx.x;
    int i = blockIdx.x * SCAN_BS + tid;
    int c = (i < NNODES) ? g_cnt[i] : 0;
    int v = (c + 3) & ~3;
    s[tid] = v;
    if (i < NNODES) {
        float dg = (float)g_degs[i];
        g_dinv[i] = (dg > 0.f) ? rsqrtf(dg) : 0.f;
    }
    __syncthreads();
    for (int d = 1; d < SCAN_BS; d <<= 1) {
        int t = (tid >= d) ? s[tid - d] : 0;
        __syncthreads();
        s[tid] += t;
        __syncthreads();
    }
    if (tid == SCAN_BS - 1) sbase = atomicAdd(&g_total, s[tid]);
    __syncthreads();
    if (i < NNODES) {
        int off = sbase + s[tid] - v;
        g_off[i] = off;
        for (int j = c; j < v; j++) g_csr[off + j] = 0ULL;   // zero pads
    }
}

// L3 (fused): blocks [0,12500) scatter edges; blocks [12500,37500) mlp0 -> A
#define SCAT_BLKS 12500
__global__ __launch_bounds__(256) void k_scatter_mlp0(const void* __restrict__ ei,
                                                      const float* __restrict__ x,
                                                      const float* __restrict__ W0,
                                                      const float* __restrict__ b0) {
    if (blockIdx.x < SCAT_BLKS) {
        __shared__ int s64;
        if (threadIdx.x == 0) s64 = probe64(ei) ? 1 : 0;
        __syncthreads();
        int e = blockIdx.x * 256 + threadIdx.x;
        if (e < NEDGES) {
            int s, d;
            if (s64) {
                s = (int)reinterpret_cast<const long long*>(ei)[e];
                d = (int)reinterpret_cast<const long long*>(ei)[NEDGES + e];
            } else {
                s = reinterpret_cast<const int*>(ei)[e];
                d = reinterpret_cast<const int*>(ei)[NEDGES + e];
            }
            s = min(max(s, 0), NNODES - 1);
            d = min(max(d, 0), NNODES - 1);
            unsigned wb = __float_as_uint(-g_dinv[s] * g_dinv[d]);
            int pos = g_off[d] + atomicAdd(&g_cur[d], 1);
            g_csr[pos] = (ull)(unsigned)s | ((ull)wb << 32);
        }
    } else {
        __shared__ float sW[96];
        __shared__ float sb[32];
        int tid = threadIdx.x;
        if (tid < 96) sW[tid] = W0[tid];
        if (tid < 32) sb[tid] = b0[tid];
        __syncthreads();
        int node = (blockIdx.x - SCAT_BLKS) * 8 + (tid >> 5);
        int o = tid & 31;
        if (node < NNODES) {
            float x0 = x[node * 3 + 0];
            float x1 = x[node * 3 + 1];
            float x2 = x[node * 3 + 2];
            float a = sb[o] + x0 * sW[o] + x1 * sW[32 + o] + x2 * sW[64 + o];
            g_A[node * HIDF + o] = fmaxf(a, 0.f);
        }
    }
}

// Prop1: 2 nodes/warp, lanes = 2 nodes x 2 pair-slots x 8 feature-lanes.
// Paired CSR LDG.128 + full-row gathers -> 1 L1 wavefront/edge, 8 edges in flight.
__global__ __launch_bounds__(256) void k_prop(const float* __restrict__ x,
                                              float* __restrict__ y) {
    int warpId = (blockIdx.x * 256 + threadIdx.x) >> 5;
    int lane = threadIdx.x & 31;
    int nd = lane >> 4;
    int es = (lane >> 3) & 1;
    int fg = lane & 7;
    int node = warpId * 2 + nd;
    int beg = __ldg(&g_off[node]);
    int deg = __ldg(&g_cnt[node]);
    int end = beg + ((deg + 3) & ~3);

    ull a0 = 0, a1 = 0;
#pragma unroll 2
    for (int i = beg + 2 * es; i < end; i += 4) {
        ulonglong2 pr = __ldg(reinterpret_cast<const ulonglong2*>(&g_csr[i]));
        int   sa = (int)(unsigned)pr.x;
        float wa = __uint_as_float((unsigned)(pr.x >> 32));
        int   sb = (int)(unsigned)pr.y;
        float wb = __uint_as_float((unsigned)(pr.y >> 32));
        float4 va = __ldg(reinterpret_cast<const float4*>(x + sa * HIDF) + fg);
        float4 vb = __ldg(reinterpret_cast<const float4*>(x + sb * HIDF) + fg);
        ull wpa = packf2(wa, wa);
        ull wpb = packf2(wb, wb);
        fmaf2v(a0, wpa, va.x, va.y);
        fmaf2v(a1, wpa, va.z, va.w);
        fmaf2v(a0, wpb, vb.x, vb.y);
        fmaf2v(a1, wpb, vb.z, vb.w);
    }

    float f0, f1, f2, f3;
    unpackf2(a0, f0, f1); unpackf2(a1, f2, f3);

    const unsigned FULL = 0xffffffffu;
    f0 += __shfl_xor_sync(FULL, f0, 8);
    f1 += __shfl_xor_sync(FULL, f1, 8);
    f2 += __shfl_xor_sync(FULL, f2, 8);
    f3 += __shfl_xor_sync(FULL, f3, 8);

    if (es == 0) {
        *reinterpret_cast<float4*>(y + node * HIDF + fg * 4) =
            make_float4(f0, f1, f2, f3);
    }
}

// Fused prop2 + combine: 512 threads, 32 nodes/block.
// Phase 1 (prop layout identical to k_prop, 16 warps): P2 row = L·T1 in regs.
// Phase 2: GEMM out = relu(T0@W0 + T1@W1 + (2P2-T0)@W2 + b [+resid]) [+ head].
// NO cleanup here (reads g_cnt/g_off — zeroing must stay in k_zero).
template <bool RESID, bool FINAL>
__global__ __launch_bounds__(512) void k_prop_combine(
    const float* __restrict__ T0,   // conv input X
    const float* __restrict__ T1,   // L·X (gather source)
    const float* __restrict__ W,    // [3,32,32]
    const float* __restrict__ bias,
    const float* __restrict__ resid,
    float* __restrict__ out,
    const float* __restrict__ W1,
    const float* __restrict__ b1)
{
    __shared__ __align__(16) float sW[3 * 32 * 32];   // 12 KB
    __shared__ __align__(16) float sT[32 * 100];      // 12.8 KB
    __shared__ __align__(16) float sb[32];
    __shared__ __align__(16) float sW1[32];

    int tid = threadIdx.x;
    for (int i = tid; i < 3072; i += 512) sW[i] = W[i];
    if (tid < 32) {
        sb[tid] = bias[tid];
        if (FINAL) sW1[tid] = W1[tid];
    }

    int nodeBase = blockIdx.x * 32;

    // ---- phase 1: propagation for this block's 32 nodes ----
    {
        int warp = tid >> 5;            // 0..15
        int lane = tid & 31;
        int nd = lane >> 4;
        int es = (lane >> 3) & 1;
        int fg = lane & 7;
        int nl = warp * 2 + nd;         // 0..31
        int node = nodeBase + nl;
        int beg = __ldg(&g_off[node]);
        int deg = __ldg(&g_cnt[node]);
        int end = beg + ((deg + 3) & ~3);

        ull a0 = 0, a1 = 0;
#pragma unroll 2
        for (int i = beg + 2 * es; i < end; i += 4) {
            ulonglong2 pr = __ldg(reinterpret_cast<const ulonglong2*>(&g_csr[i]));
            int   sa = (int)(unsigned)pr.x;
            float wa = __uint_as_float((unsigned)(pr.x >> 32));
            int   sb2 = (int)(unsigned)pr.y;
            float wb = __uint_as_float((unsigned)(pr.y >> 32));
            float4 va = __ldg(reinterpret_cast<const float4*>(T1 + sa * HIDF) + fg);
            float4 vb = __ldg(reinterpret_cast<const float4*>(T1 + sb2 * HIDF) + fg);
            ull wpa = packf2(wa, wa);
            ull wpb = packf2(wb, wb);
            fmaf2v(a0, wpa, va.x, va.y);
            fmaf2v(a1, wpa, va.z, va.w);
            fmaf2v(a0, wpb, vb.x, vb.y);
            fmaf2v(a1, wpb, vb.z, vb.w);
        }

        float p0, p1, p2, p3;
        unpackf2(a0, p0, p1); unpackf2(a1, p2, p3);

        const unsigned FULL = 0xffffffffu;
        p0 += __shfl_xor_sync(FULL, p0, 8);
        p1 += __shfl_xor_sync(FULL, p1, 8);
        p2 += __shfl_xor_sync(FULL, p2, 8);
        p3 += __shfl_xor_sync(FULL, p3, 8);

        if (es == 0) {
            int gidx = node * HIDF + fg * 4;
            float4 t0 = __ldg(reinterpret_cast<const float4*>(T0 + gidx));
            float4 t1 = __ldg(reinterpret_cast<const float4*>(T1 + gidx));
            float* st = &sT[nl * 100 + fg * 4];
            *reinterpret_cast<float4*>(st)      = t0;
            *reinterpret_cast<float4*>(st + 32) = t1;
            *reinterpret_cast<float4*>(st + 64) =
                make_float4(2.f * p0 - t0.x, 2.f * p1 - t0.y,
                            2.f * p2 - t0.z, 2.f * p3 - t0.w);
        }
    }
    __syncthreads();

    // ---- phase 2: per-node GEMM, 16 threads/node, 2 outputs/thread ----
    {
        int nl = tid >> 4;              // 0..31
        int ot = tid & 15;
        int og = ot * 2;
        int node = nodeBase + nl;

        ull acc = __double_as_longlong(*reinterpret_cast<const double*>(sb + og));
        const float* tp = &sT[nl * 100];
#pragma unroll 8
        for (int k = 0; k < 96; k++) {
            float t = tp[k];
            ull w01 = __double_as_longlong(
                *reinterpret_cast<const double*>(sW + k * 32 + og));
            fmaf2(acc, packf2(t, t), w01);
        }
        float f0, f1;
        unpackf2(acc, f0, f1);

        int gi = node * HIDF + og;
        if (RESID) {
            float2 r = *reinterpret_cast<const float2*>(resid + gi);
            f0 += r.x; f1 += r.y;
        }
        f0 = fmaxf(f0, 0.f);
        f1 = fmaxf(f1, 0.f);

        if (!FINAL) {
            *reinterpret_cast<float2*>(out + gi) = make_float2(f0, f1);
        } else {
            float p = f0 * sW1[og] + f1 * sW1[og + 1];
            const unsigned FULL = 0xffffffffu;
            p += __shfl_xor_sync(FULL, p, 1);
            p += __shfl_xor_sync(FULL, p, 2);
            p += __shfl_xor_sync(FULL, p, 4);
            p += __shfl_xor_sync(FULL, p, 8);
            if (ot == 0) out[node] = p + b1[0];
        }
    }
}

// ---------------- host ----------------
extern "C" void kernel_launch(void* const* d_in, const int* in_sizes, int n_in,
                              void* d_out, int out_size) {
    const float* x    = (const float*)d_in[0];
    const void*  ei   = d_in[1];
    const float* W0   = (const float*)d_in[2];
    const float* b0   = (const float*)d_in[3];
    const float* c11W = (const float*)d_in[4];
    const float* c11b = (const float*)d_in[5];
    const float* c12W = (const float*)d_in[6];
    const float* c12b = (const float*)d_in[7];
    const float* c21W = (const float*)d_in[8];
    const float* c21b = (const float*)d_in[9];
    const float* c22W = (const float*)d_in[10];
    const float* c22b = (const float*)d_in[11];
    const float* W1   = (const float*)d_in[12];
    const float* b1   = (const float*)d_in[13];
    float*       out  = (float*)d_out;

    float *A, *B, *D;
    cudaGetSymbolAddress((void**)&A, g_A);
    cudaGetSymbolAddress((void**)&B, g_B);
    cudaGetSymbolAddress((void**)&D, g_D);

    const int TB = 256;
    const int gb_edges = (NEDGES + TB - 1) / TB;   // 12500
    const int gb_prop  = (NNODES / 2) * 32 / TB;   // 12500 exact (2 nodes/warp)
    const int gb_fuse  = NNODES / 32;              // 6250 exact (32 nodes/block)
    const int gb_zero  = (NNODES / 4 + TB - 1) / TB;

    // setup: 4 launches
    k_zero<<<gb_zero, TB>>>();
    k_hist<<<gb_edges, TB>>>(ei);
    k_scan<<<NBLK_SCAN, SCAN_BS>>>();
    k_scatter_mlp0<<<SCAT_BLKS + 25000, TB>>>(ei, x, W0, b0);

    // ---- block 1, conv 1: D = relu(cheb(A)) ----
    k_prop<<<gb_prop, TB>>>(A, B);
    k_prop_combine<false, false><<<gb_fuse, 512>>>(A, B, c11W, c11b, nullptr, D, nullptr, nullptr);

    // ---- block 1, conv 2: A = relu(cheb(D) + A) ----
    k_prop<<<gb_prop, TB>>>(D, B);
    k_prop_combine<true, false><<<gb_fuse, 512>>>(D, B, c12W, c12b, A, A, nullptr, nullptr);

    // ---- block 2, conv 1: D = relu(cheb(A)) ----
    k_prop<<<gb_prop, TB>>>(A, B);
    k_prop_combine<false, false><<<gb_fuse, 512>>>(A, B, c21W, c21b, nullptr, D, nullptr, nullptr);

    // ---- block 2, conv 2 + head ----
    k_prop<<<gb_prop, TB>>>(D, B);
    k_prop_combine<true, true><<<gb_fuse, 512>>>(D, B, c22W, c22b, A, out, W1, b1);
}

// round 14
// speedup vs baseline: 1.3694x; 1.3694x over previous
#include <cuda_runtime.h>

#define NNODES 200000
#define NEDGES 3200000
#define HIDF 32
#define SCAN_BS 1024
#define NBLK_SCAN 196           // 196*1024 >= NNODES
#define CSR_CAP (NEDGES + 4 * NNODES)
typedef unsigned long long ull;

// ---------------- device scratch (static, zero-init at load) ----------------
__device__ int   g_is64;
__device__ int   g_degs[NNODES];   // src-degree
__device__ int   g_cnt[NNODES];    // dst-degree
__device__ int   g_cur[NNODES];    // scatter cursors
__device__ int   g_off[NNODES];    // padded CSR segment starts
__device__ int   g_total;          // atomic base for scan
__device__ float g_ps[NNODES];     // prop out scale  = -s*dinv  (= -1/deg or 0)
__device__ float g_invs[NNODES];   // 1/s  (sqrt(deg) or 1)
__device__ float g_sarr[NNODES];   // s    (dinv or 1)
__device__ int   g_csri[CSR_CAP];  // src index per edge; pads = NNODES (zero row)
// feature buffers in SCALED space; row NNODES is permanently zero (never written)
__device__ float g_A[(NNODES + 1) * HIDF];
__device__ float g_B[(NNODES + 1) * HIDF];
__device__ float g_C[(NNODES + 1) * HIDF];
__device__ float g_D[(NNODES + 1) * HIDF];

// ---------------- f32x2 helpers ----------------
__device__ __forceinline__ ull packf2(float x, float y) {
    ull r; asm("mov.b64 %0, {%1, %2};" : "=l"(r) : "f"(x), "f"(y)); return r;
}
__device__ __forceinline__ void unpackf2(ull v, float& x, float& y) {
    asm("mov.b64 {%0, %1}, %2;" : "=f"(x), "=f"(y) : "l"(v));
}
__device__ __forceinline__ void fmaf2(ull& a, ull b, ull c) {
    asm("fma.rn.f32x2 %0, %1, %2, %0;" : "+l"(a) : "l"(b), "l"(c));
}
__device__ __forceinline__ void addf2v(ull& a, float x, float y) {
    ull v; asm("mov.b64 %0, {%1, %2};" : "=l"(v) : "f"(x), "f"(y));
    asm("add.rn.f32x2 %0, %0, %1;" : "+l"(a) : "l"(v));
}

// L0: zero per-call state + dtype probe (once).
__global__ void k_zero(const long long* __restrict__ ei) {
    int i = blockIdx.x * blockDim.x + threadIdx.x;
    if (i == 0) {
        bool ok = true;
        for (int j = 0; j < 64; j++) { long long v = ei[j]; ok &= (v >= 0 && v < NNODES); }
        g_is64 = ok ? 1 : 0;
        g_total = 0;
    }
    if (i < NNODES / 4) {
        int4 z = make_int4(0, 0, 0, 0);
        reinterpret_cast<int4*>(g_degs)[i] = z;
        reinterpret_cast<int4*>(g_cnt)[i]  = z;
        reinterpret_cast<int4*>(g_cur)[i]  = z;
    }
}

// L1: degree histograms
__global__ void k_hist(const void* __restrict__ ei) {
    int e = blockIdx.x * blockDim.x + threadIdx.x;
    if (e < NEDGES) {
        int s, d;
        if (g_is64) {
            s = (int)reinterpret_cast<const long long*>(ei)[e];
            d = (int)reinterpret_cast<const long long*>(ei)[NEDGES + e];
        } else {
            s = reinterpret_cast<const int*>(ei)[e];
            d = reinterpret_cast<const int*>(ei)[NEDGES + e];
        }
        s = min(max(s, 0), NNODES - 1);
        d = min(max(d, 0), NNODES - 1);
        atomicAdd(&g_degs[s], 1);
        atomicAdd(&g_cnt[d], 1);
    }
}

// L2: padded scan + per-node scale factors + pad slots -> NNODES (zero row).
__global__ __launch_bounds__(SCAN_BS) void k_scan() {
    __shared__ int s[SCAN_BS];
    __shared__ int sbase;
    int tid = threadIdx.x;
    int i = blockIdx.x * SCAN_BS + tid;
    int c = (i < NNODES) ? g_cnt[i] : 0;
    int v = (c + 3) & ~3;
    s[tid] = v;
    if (i < NNODES) {
        float dg = (float)g_degs[i];
        if (dg > 0.f) {
            float dinv = rsqrtf(dg);
            g_ps[i]   = -dinv * dinv;     // -s*dinv
            g_invs[i] = 1.f / dinv;       // sqrt(deg)
            g_sarr[i] = dinv;
        } else {
            g_ps[i]   = 0.f;
            g_invs[i] = 1.f;
            g_sarr[i] = 1.f;
        }
    }
    __syncthreads();
    for (int d = 1; d < SCAN_BS; d <<= 1) {
        int t = (tid >= d) ? s[tid - d] : 0;
        __syncthreads();
        s[tid] += t;
        __syncthreads();
    }
    if (tid == SCAN_BS - 1) sbase = atomicAdd(&g_total, s[tid]);
    __syncthreads();
    if (i < NNODES) {
        int off = sbase + s[tid] - v;
        g_off[i] = off;
        for (int j = c; j < v; j++) g_csri[off + j] = NNODES;   // pads -> zero row
    }
}

// L3 (fused): blocks [0,12500) scatter src indices; rest: mlp0 -> scaled A
#define SCAT_BLKS 12500
__global__ __launch_bounds__(256) void k_scatter_mlp0(const void* __restrict__ ei,
                                                      const float* __restrict__ x,
                                                      const float* __restrict__ W0,
                                                      const float* __restrict__ b0) {
    if (blockIdx.x < SCAT_BLKS) {
        int e = blockIdx.x * 256 + threadIdx.x;
        if (e < NEDGES) {
            int s, d;
            if (g_is64) {
                s = (int)reinterpret_cast<const long long*>(ei)[e];
                d = (int)reinterpret_cast<const long long*>(ei)[NEDGES + e];
            } else {
                s = reinterpret_cast<const int*>(ei)[e];
                d = reinterpret_cast<const int*>(ei)[NEDGES + e];
            }
            s = min(max(s, 0), NNODES - 1);
            d = min(max(d, 0), NNODES - 1);
            int pos = g_off[d] + atomicAdd(&g_cur[d], 1);
            g_csri[pos] = s;
        }
    } else {
        __shared__ float sW[96];
        __shared__ float sb[32];
        int tid = threadIdx.x;
        if (tid < 96) sW[tid] = W0[tid];
        if (tid < 32) sb[tid] = b0[tid];
        __syncthreads();
        int node = (blockIdx.x - SCAT_BLKS) * 8 + (tid >> 5);
        int o = tid & 31;
        if (node < NNODES) {
            float x0 = x[node * 3 + 0];
            float x1 = x[node * 3 + 1];
            float x2 = x[node * 3 + 2];
            float a = sb[o] + x0 * sW[o] + x1 * sW[32 + o] + x2 * sW[64 + o];
            g_A[node * HIDF + o] = g_sarr[node] * fmaxf(a, 0.f);   // scaled store
        }
    }
}

// Prop (scaled space): UNWEIGHTED neighbor sum, then per-node factor g_ps.
// 2 nodes/warp, 2 slots x 8 fg lanes; slot loads int2 of srcs; full-row gathers
// keep 1 L1 wavefront/edge; pads gather the zero row (exact no-op).
__global__ __launch_bounds__(256) void k_prop(const float* __restrict__ x,
                                              float* __restrict__ y) {
    int warpId = (blockIdx.x * 256 + threadIdx.x) >> 5;
    int lane = threadIdx.x & 31;
    int nd = lane >> 4;
    int es = (lane >> 3) & 1;
    int fg = lane & 7;
    int node = warpId * 2 + nd;
    int beg = __ldg(&g_off[node]);
    int deg = __ldg(&g_cnt[node]);
    int end = beg + ((deg + 3) & ~3);

    ull a0 = 0, a1 = 0;
#pragma unroll 2
    for (int i = beg + 2 * es; i < end; i += 4) {
        int2 s2 = __ldg(reinterpret_cast<const int2*>(&g_csri[i]));
        float4 va = __ldg(reinterpret_cast<const float4*>(x + s2.x * HIDF) + fg);
        float4 vb = __ldg(reinterpret_cast<const float4*>(x + s2.y * HIDF) + fg);
        addf2v(a0, va.x, va.y);
        addf2v(a1, va.z, va.w);
        addf2v(a0, vb.x, vb.y);
        addf2v(a1, vb.z, vb.w);
    }

    float f0, f1, f2, f3;
    unpackf2(a0, f0, f1); unpackf2(a1, f2, f3);

    const unsigned FULL = 0xffffffffu;
    f0 += __shfl_xor_sync(FULL, f0, 8);
    f1 += __shfl_xor_sync(FULL, f1, 8);
    f2 += __shfl_xor_sync(FULL, f2, 8);
    f3 += __shfl_xor_sync(FULL, f3, 8);

    if (es == 0) {
        float sc = __ldg(&g_ps[node]);
        *reinterpret_cast<float4*>(y + node * HIDF + fg * 4) =
            make_float4(sc * f0, sc * f1, sc * f2, sc * f3);
    }
}

// Combine (scaled in, scaled out): weights pre-transformed so staging = copies.
//   out_true = inv_s*(T0s@(W0-W2) + T1s@W1 + T2s@(2W2) [+ Rs]) + bias
//   store s*relu(out_true); FINAL: head dot on true values.
template <bool RESID, bool FINAL>
__global__ __launch_bounds__(256) void k_combine(const float* __restrict__ T0,
                                                 const float* __restrict__ T1,
                                                 const float* __restrict__ P2,
                                                 const float* __restrict__ W,
                                                 const float* __restrict__ bias,
                                                 const float* __restrict__ resid,
                                                 float* __restrict__ out,
                                                 const float* __restrict__ W1,
                                                 const float* __restrict__ b1) {
    __shared__ __align__(16) float sW[3 * 32 * 32];
    __shared__ __align__(16) float sT[64 * 100];
    __shared__ __align__(16) float sb[32];
    __shared__ __align__(16) float sW1[32];

    int tid = threadIdx.x;
    for (int i = tid; i < 1024; i += 256) {
        float w2 = W[2048 + i];
        sW[i]        = W[i] - w2;
        sW[1024 + i] = W[1024 + i];
        sW[2048 + i] = 2.f * w2;
    }
    if (tid < 32) {
        sb[tid] = bias[tid];
        if (FINAL) sW1[tid] = W1[tid];
    }
    int nodeBase = blockIdx.x * 64;
    {
        int node = tid >> 2;           // 0..63
        int part = tid & 3;
        int gidx = (nodeBase + node) * HIDF + part * 8;
        float4 u00 = *reinterpret_cast<const float4*>(T0 + gidx);
        float4 u01 = *reinterpret_cast<const float4*>(T0 + gidx + 4);
        float4 u10 = *reinterpret_cast<const float4*>(T1 + gidx);
        float4 u11 = *reinterpret_cast<const float4*>(T1 + gidx + 4);
        float4 u20 = *reinterpret_cast<const float4*>(P2 + gidx);
        float4 u21 = *reinterpret_cast<const float4*>(P2 + gidx + 4);
        float* st = &sT[node * 100 + part * 8];
        *reinterpret_cast<float4*>(st)      = u00;
        *reinterpret_cast<float4*>(st + 4)  = u01;
        *reinterpret_cast<float4*>(st + 32) = u10;
        *reinterpret_cast<float4*>(st + 36) = u11;
        *reinterpret_cast<float4*>(st + 64) = u20;
        *reinterpret_cast<float4*>(st + 68) = u21;
    }
    __syncthreads();

    int ng = tid >> 3;                 // 0..31
    int og = (tid & 7) * 4;
    int n0 = ng * 2, n1 = n0 + 1;
    int node0 = nodeBase + n0, node1 = nodeBase + n1;

    ull a00 = 0, a01 = 0, a10 = 0, a11 = 0;
    const float* t0p = &sT[n0 * 100];
    const float* t1p = &sT[n1 * 100];
#pragma unroll 8
    for (int k = 0; k < 96; k++) {
        float t0 = t0p[k];
        float t1 = t1p[k];
        ull tp0 = packf2(t0, t0);
        ull tp1 = packf2(t1, t1);
        double2 wv = *reinterpret_cast<const double2*>(sW + k * 32 + og);
        ull w01 = __double_as_longlong(wv.x);
        ull w23 = __double_as_longlong(wv.y);
        fmaf2(a00, tp0, w01);
        fmaf2(a01, tp0, w23);
        fmaf2(a10, tp1, w01);
        fmaf2(a11, tp1, w23);
    }

    float f0, f1, f2, f3, f4, f5, f6, f7;
    unpackf2(a00, f0, f1); unpackf2(a01, f2, f3);
    unpackf2(a10, f4, f5); unpackf2(a11, f6, f7);

    int gi0 = node0 * HIDF + og;
    int gi1 = node1 * HIDF + og;
    if (RESID) {   // resid stored in scaled space with the SAME per-node s
        float4 r0 = *reinterpret_cast<const float4*>(resid + gi0);
        float4 r1 = *reinterpret_cast<const float4*>(resid + gi1);
        f0 += r0.x; f1 += r0.y; f2 += r0.z; f3 += r0.w;
        f4 += r1.x; f5 += r1.y; f6 += r1.z; f7 += r1.w;
    }
    float is0 = __ldg(&g_invs[node0]);
    float is1 = __ldg(&g_invs[node1]);
    // true pre-activation = inv_s*acc + bias ; relu
    f0 = fmaxf(f0 * is0 + sb[og],     0.f);
    f1 = fmaxf(f1 * is0 + sb[og + 1], 0.f);
    f2 = fmaxf(f2 * is0 + sb[og + 2], 0.f);
    f3 = fmaxf(f3 * is0 + sb[og + 3], 0.f);
    f4 = fmaxf(f4 * is1 + sb[og],     0.f);
    f5 = fmaxf(f5 * is1 + sb[og + 1], 0.f);
    f6 = fmaxf(f6 * is1 + sb[og + 2], 0.f);
    f7 = fmaxf(f7 * is1 + sb[og + 3], 0.f);

    if (!FINAL) {
        float s0 = __ldg(&g_sarr[node0]);
        float s1 = __ldg(&g_sarr[node1]);
        *reinterpret_cast<float4*>(out + gi0) =
            make_float4(s0 * f0, s0 * f1, s0 * f2, s0 * f3);
        *reinterpret_cast<float4*>(out + gi1) =
            make_float4(s1 * f4, s1 * f5, s1 * f6, s1 * f7);
    } else {
        float p0 = f0 * sW1[og] + f1 * sW1[og + 1] + f2 * sW1[og + 2] + f3 * sW1[og + 3];
        float p1 = f4 * sW1[og] + f5 * sW1[og + 1] + f6 * sW1[og + 2] + f7 * sW1[og + 3];
        const unsigned FULL = 0xffffffffu;
        p0 += __shfl_xor_sync(FULL, p0, 1);
        p1 += __shfl_xor_sync(FULL, p1, 1);
        p0 += __shfl_xor_sync(FULL, p0, 2);
        p1 += __shfl_xor_sync(FULL, p1, 2);
        p0 += __shfl_xor_sync(FULL, p0, 4);
        p1 += __shfl_xor_sync(FULL, p1, 4);
        if ((tid & 7) == 0) {
            float bb = b1[0];
            out[nodeBase + n0] = p0 + bb;
            out[nodeBase + n1] = p1 + bb;
        }
    }
}

// ---------------- host ----------------
extern "C" void kernel_launch(void* const* d_in, const int* in_sizes, int n_in,
                              void* d_out, int out_size) {
    const float* x    = (const float*)d_in[0];
    const void*  ei   = d_in[1];
    const float* W0   = (const float*)d_in[2];
    const float* b0   = (const float*)d_in[3];
    const float* c11W = (const float*)d_in[4];
    const float* c11b = (const float*)d_in[5];
    const float* c12W = (const float*)d_in[6];
    const float* c12b = (const float*)d_in[7];
    const float* c21W = (const float*)d_in[8];
    const float* c21b = (const float*)d_in[9];
    const float* c22W = (const float*)d_in[10];
    const float* c22b = (const float*)d_in[11];
    const float* W1   = (const float*)d_in[12];
    const float* b1   = (const float*)d_in[13];
    float*       out  = (float*)d_out;

    float *A, *B, *C, *D;
    cudaGetSymbolAddress((void**)&A, g_A);
    cudaGetSymbolAddress((void**)&B, g_B);
    cudaGetSymbolAddress((void**)&C, g_C);
    cudaGetSymbolAddress((void**)&D, g_D);

    const int TB = 256;
    const int gb_edges = (NEDGES + TB - 1) / TB;   // 12500
    const int gb_prop  = (NNODES / 2) * 32 / TB;   // 12500 exact
    const int gb_comb  = NNODES / 64;              // 3125 exact
    const int gb_zero  = (NNODES / 4 + TB - 1) / TB;

    // setup
    k_zero<<<gb_zero, TB>>>((const long long*)ei);
    k_hist<<<gb_edges, TB>>>(ei);
    k_scan<<<NBLK_SCAN, SCAN_BS>>>();
    k_scatter_mlp0<<<SCAT_BLKS + 25000, TB>>>(ei, x, W0, b0);

    // ---- block 1, conv 1: D = scaled relu(cheb(A)) ----
    k_prop<<<gb_prop, TB>>>(A, B);
    k_prop<<<gb_prop, TB>>>(B, C);
    k_combine<false, false><<<gb_comb, TB>>>(A, B, C, c11W, c11b, nullptr, D, nullptr, nullptr);

    // ---- block 1, conv 2: A = scaled relu(cheb(D) + A) ----
    k_prop<<<gb_prop, TB>>>(D, B);
    k_prop<<<gb_prop, TB>>>(B, C);
    k_combine<true, false><<<gb_comb, TB>>>(D, B, C, c12W, c12b, A, A, nullptr, nullptr);

    // ---- block 2, conv 1: D = scaled relu(cheb(A)) ----
    k_prop<<<gb_prop, TB>>>(A, B);
    k_prop<<<gb_prop, TB>>>(B, C);
    k_combine<false, false><<<gb_comb, TB>>>(A, B, C, c21W, c21b, nullptr, D, nullptr, nullptr);

    // ---- block 2, conv 2 + head ----
    k_prop<<<gb_prop, TB>>>(D, B);
    k_prop<<<gb_prop, TB>>>(B, C);
    k_combine<true, true><<<gb_comb, TB>>>(D, B, C, c22W, c22b, A, out, W1, b1);
}